// round 3
// baseline (speedup 1.0000x reference)
#include <cuda_runtime.h>
#include <math.h>

// SBEceLoss: logits [N,100] f32, labels [N] i64 -> scalar ece (f32)
//
// Pipeline (3 graph-capturable launches, no allocations):
//   1) init_kernel:  zero per-class histograms (device globals)
//   2) row_kernel:   per row -> argmax idx + accuracy flag; histogram via
//                    shared-mem int atomics, flushed with global REDs
//   3) final_kernel: 100-class x 15-bin softmax, ECE formula, write d_out[0]

#define C_CLASSES 100
#define NB 15

__device__ int g_cnt[C_CLASSES];
__device__ int g_acc[C_CLASSES];

__global__ void init_kernel() {
    int t = threadIdx.x;
    if (t < C_CLASSES) { g_cnt[t] = 0; g_acc[t] = 0; }
}

__global__ void __launch_bounds__(256)
row_kernel(const float* __restrict__ logits,
           const long long* __restrict__ labels,
           int n_rows) {
    __shared__ int s_cnt[C_CLASSES];
    __shared__ int s_acc[C_CLASSES];
    for (int i = threadIdx.x; i < C_CLASSES; i += blockDim.x) { s_cnt[i] = 0; s_acc[i] = 0; }
    __syncthreads();

    const int lane = threadIdx.x & 31;
    const int gw   = blockIdx.x * (blockDim.x >> 5) + (threadIdx.x >> 5);
    const int nw   = gridDim.x * (blockDim.x >> 5);
    const float NEG = __int_as_float(0xff800000);  // -inf

    for (int row = gw; row < n_rows; row += nw) {
        // 100 floats = 25 float4 per row (row stride 400B, 16B aligned).
        float4 v;
        if (lane < 25) {
            v = __ldg(reinterpret_cast<const float4*>(logits + (size_t)row * C_CLASSES) + lane);
        } else {
            v = make_float4(NEG, NEG, NEG, NEG);
        }

        // Per-thread top-2 + first-occurrence argmax over 4 consecutive cols.
        float m = v.x; int idx = lane * 4; float m2 = NEG;
        { bool p = v.y > m; m2 = p ? m : fmaxf(m2, v.y); if (p) { m = v.y; idx = lane * 4 + 1; } }
        { bool p = v.z > m; m2 = p ? m : fmaxf(m2, v.z); if (p) { m = v.z; idx = lane * 4 + 2; } }
        { bool p = v.w > m; m2 = p ? m : fmaxf(m2, v.w); if (p) { m = v.w; idx = lane * 4 + 3; } }

        // Warp butterfly top-2 reduce (associative: winner by (value desc, idx asc);
        // second = max(winner.m2, loser.m) since loser.m >= loser.m2).
        #pragma unroll
        for (int off = 16; off; off >>= 1) {
            float om  = __shfl_xor_sync(0xffffffffu, m,   off);
            int   oi  = __shfl_xor_sync(0xffffffffu, idx, off);
            float om2 = __shfl_xor_sync(0xffffffffu, m2,  off);
            bool win = (m > om) || (m == om && idx < oi);
            if (win) { m2 = fmaxf(m2, om); }
            else     { m2 = fmaxf(om2, m); m = om; idx = oi; }
        }

        // accuracy = (max_logprob == (float)label). Filter: if gap < 12 and
        // |m| < 16 then sumexp >= 1 + e^-12, log(sumexp) >= 6.0e-6 > ulp(16)/2,
        // so lse > m strictly -> pred < 0 -> never equals a label in [0,100).
        int acc = 0;
        float gap = m - m2;
        if (!(gap < 12.0f && fabsf(m) < 16.0f)) {
            // Exact (reference-faithful) fallback; statistically never taken.
            float s = 0.0f;
            if (lane < 25)
                s = expf(v.x - m) + expf(v.y - m) + expf(v.z - m) + expf(v.w - m);
            #pragma unroll
            for (int off = 16; off; off >>= 1)
                s += __shfl_xor_sync(0xffffffffu, s, off);
            float lse  = m + logf(s);
            float pred = m - lse;
            float lab  = (float)labels[row];
            acc = (pred == lab) ? 1 : 0;
        }

        if (lane == 0) {
            atomicAdd(&s_cnt[idx], 1);
            if (acc) atomicAdd(&s_acc[idx], 1);
        }
    }

    __syncthreads();
    for (int i = threadIdx.x; i < C_CLASSES; i += blockDim.x) {
        int c = s_cnt[i]; if (c) atomicAdd(&g_cnt[i], c);
        int a = s_acc[i]; if (a) atomicAdd(&g_acc[i], a);
    }
}

// Deterministic finalize: thread b (0..14) owns bin b, loops all 100 classes.
__global__ void final_kernel(float* __restrict__ out) {
    __shared__ float s_sum[NB];   // sum_coeffs[b]
    __shared__ float s_conf[NB];  // sum(conf * coeff)[b]
    __shared__ float s_accs[NB];  // sum(acc  * coeff)[b]

    int b = threadIdx.x;
    if (b < NB) {
        float sum_c = 0.0f, sum_cc = 0.0f, sum_a = 0.0f;
        for (int c = 0; c < C_CLASSES; c++) {
            int cnt = g_cnt[c];
            int ac  = g_acc[c];
            if ((cnt | ac) == 0) continue;
            float cf = (float)c;
            // softmax over bins of -(c - anchor)^2 / 0.01 (float32, as reference)
            float d[NB];
            float dmax = __int_as_float(0xff800000);
            #pragma unroll
            for (int j = 0; j < NB; j++) {
                float aj = (float)((2 * j + 1) / 30.0);
                float t  = cf - aj;
                d[j] = -(t * t) / 0.01f;
                dmax = fmaxf(dmax, d[j]);
            }
            float denom = 0.0f;
            #pragma unroll
            for (int j = 0; j < NB; j++) denom += expf(d[j] - dmax);
            float coeff = expf(d[b] - dmax) / denom;

            float fcnt = (float)cnt;         // exact: cnt < 2^24
            sum_c  += fcnt * coeff;
            sum_cc += fcnt * cf * coeff;
            sum_a  += (float)ac * coeff;
        }
        s_sum[b]  = sum_c;
        s_conf[b] = sum_cc;
        s_accs[b] = sum_a;
    }
    __syncthreads();

    if (threadIdx.x == 0) {
        float tot = 0.0f;
        #pragma unroll
        for (int j = 0; j < NB; j++) tot += fabsf(s_sum[j]);
        float wden = fmaxf(tot, 1e-5f);
        float acc2 = 0.0f;
        #pragma unroll
        for (int j = 0; j < NB; j++) {
            float den = fmaxf(s_sum[j], 1e-5f);
            float bc  = s_conf[j] / den;
            float ba  = s_accs[j] / den;
            float w   = s_sum[j] / wden;
            float df  = bc - ba;
            acc2 += df * df * w;
        }
        out[0] = sqrtf(acc2);
    }
}

extern "C" void kernel_launch(void* const* d_in, const int* in_sizes, int n_in,
                              void* d_out, int out_size) {
    const float*     logits = (const float*)d_in[0];
    const long long* labels = (const long long*)d_in[1];
    float*           out    = (float*)d_out;
    int n_rows = in_sizes[1];  // labels count = N

    init_kernel<<<1, 128>>>();
    row_kernel<<<1184, 256>>>(logits, labels, n_rows);
    final_kernel<<<1, 32>>>(out);
}

// round 4
// speedup vs baseline: 2.0235x; 2.0235x over previous
#include <cuda_runtime.h>
#include <math.h>

// SBEceLoss: logits [N,100] f32, labels [N] i64 -> scalar ece (f32)
//
// 2 graph-capturable launches, no allocations:
//   1) row_kernel:   warp-per-row (x4 rows/iter), REDUX argmax+top2,
//                    gap-filter accuracy, shared-mem histogram -> global REDs
//   2) final_kernel: 100-class x 15-bin softmax + ECE; then re-zeros the
//                    device histograms (so every graph replay starts clean;
//                    static zero-init covers the very first call).

#define C_CLASSES 100
#define NB 15
#define FULLM 0xffffffffu

__device__ int g_cnt[C_CLASSES];
__device__ int g_acc[C_CLASSES];

// Order-preserving float->uint encoding (and inverse).
__device__ __forceinline__ unsigned fenc(float f) {
    unsigned u = __float_as_uint(f);
    return u ^ ((unsigned)((int)u >> 31) | 0x80000000u);
}
__device__ __forceinline__ float fdec(unsigned e) {
    unsigned mask = (~(unsigned)((int)e >> 31)) | 0x80000000u;
    return __uint_as_float(e ^ mask);
}

__global__ void __launch_bounds__(256)
row_kernel(const float* __restrict__ logits,
           const long long* __restrict__ labels,
           int n_rows) {
    __shared__ int s_cnt[C_CLASSES];
    __shared__ int s_acc[C_CLASSES];
    for (int i = threadIdx.x; i < C_CLASSES; i += blockDim.x) { s_cnt[i] = 0; s_acc[i] = 0; }
    __syncthreads();

    const int lane = threadIdx.x & 31;
    const int gw   = blockIdx.x * (blockDim.x >> 5) + (threadIdx.x >> 5);
    const int nw   = gridDim.x * (blockDim.x >> 5);
    const float NEG = __int_as_float(0xff800000);  // -inf

    for (long long base = (long long)gw * 4; base < n_rows; base += (long long)nw * 4) {
        // ---- issue 4 independent row loads back-to-back (MLP=4/warp) ----
        float4 v[4];
        #pragma unroll
        for (int r = 0; r < 4; r++) {
            long long row = base + r;
            if (row < n_rows && lane < 25)
                v[r] = __ldg(reinterpret_cast<const float4*>(logits + row * C_CLASSES) + lane);
            else
                v[r] = make_float4(NEG, NEG, NEG, NEG);
        }

        // ---- 4 independent reductions (ILP hides REDUX latency) ----
        #pragma unroll
        for (int r = 0; r < 4; r++) {
            long long row = base + r;          // warp-uniform -> no divergence
            if (row >= n_rows) continue;

            // per-thread top-2 + first-occurrence argmax over 4 cols
            float m = v[r].x; int idx = lane * 4; float m2 = NEG;
            { bool p = v[r].y > m; m2 = p ? m : fmaxf(m2, v[r].y); if (p) { m = v[r].y; idx = lane * 4 + 1; } }
            { bool p = v[r].z > m; m2 = p ? m : fmaxf(m2, v[r].z); if (p) { m = v[r].z; idx = lane * 4 + 2; } }
            { bool p = v[r].w > m; m2 = p ? m : fmaxf(m2, v[r].w); if (p) { m = v[r].w; idx = lane * 4 + 3; } }

            unsigned em = fenc(m);
            unsigned k1 = __reduce_max_sync(FULLM, em);
            unsigned widx = __reduce_min_sync(FULLM, (em == k1) ? (unsigned)idx : 0xffffffffu);
            bool winner = (em == k1) && ((unsigned)idx == widx);
            unsigned e2 = __reduce_max_sync(FULLM, winner ? fenc(m2) : em);

            float mg  = fdec(k1);
            float m2g = fdec(e2);

            // accuracy = (max_logprob == (float)label). If gap<12 and |m|<16:
            // sumexp >= 1 + e^-12 => log(sumexp) >= 6.0e-6 > ulp(16)/2, so the
            // max log-prob is strictly negative -> can never equal a label.
            int acc = 0;
            if (!((mg - m2g) < 12.0f && fabsf(mg) < 16.0f)) {
                // exact reference-faithful fallback (statistically never taken)
                float s = 0.0f;
                if (lane < 25)
                    s = expf(v[r].x - mg) + expf(v[r].y - mg) +
                        expf(v[r].z - mg) + expf(v[r].w - mg);
                #pragma unroll
                for (int off = 16; off; off >>= 1)
                    s += __shfl_xor_sync(FULLM, s, off);
                float pred = mg - (mg + logf(s));
                acc = (pred == (float)labels[row]) ? 1 : 0;
            }

            if (lane == 0) {
                atomicAdd(&s_cnt[widx], 1);
                if (acc) atomicAdd(&s_acc[widx], 1);
            }
        }
    }

    __syncthreads();
    for (int i = threadIdx.x; i < C_CLASSES; i += blockDim.x) {
        int c = s_cnt[i]; if (c) atomicAdd(&g_cnt[i], c);
        int a = s_acc[i]; if (a) atomicAdd(&g_acc[i], a);
    }
}

// 128 threads: threads 0..99 compute per-class bin coefficients (parallel expf),
// threads 0..14 then reduce over classes in the SAME order as before (c=0..99),
// so arithmetic is bit-identical to the validated version.
__global__ void final_kernel(float* __restrict__ out) {
    __shared__ float s_coef[C_CLASSES][NB + 1];  // +1 pad
    __shared__ int   s_c2[C_CLASSES];
    __shared__ int   s_a2[C_CLASSES];
    __shared__ float s_sum[NB], s_conf[NB], s_accs[NB];

    int t = threadIdx.x;
    if (t < C_CLASSES) {
        int cnt = g_cnt[t];
        int ac  = g_acc[t];
        s_c2[t] = cnt;
        s_a2[t] = ac;
        float cf = (float)t;
        float d[NB];
        float dmax = __int_as_float(0xff800000);
        #pragma unroll
        for (int j = 0; j < NB; j++) {
            float aj = (float)((2 * j + 1) / 30.0);
            float tt = cf - aj;
            d[j] = -(tt * tt) / 0.01f;
            dmax = fmaxf(dmax, d[j]);
        }
        float denom = 0.0f;
        #pragma unroll
        for (int j = 0; j < NB; j++) denom += expf(d[j] - dmax);
        #pragma unroll
        for (int j = 0; j < NB; j++) s_coef[t][j] = expf(d[j] - dmax) / denom;
        // consume-then-reset: safe (each thread zeroes only its own class)
        g_cnt[t] = 0;
        g_acc[t] = 0;
    }
    __syncthreads();

    if (t < NB) {
        float sum_c = 0.0f, sum_cc = 0.0f, sum_a = 0.0f;
        for (int c = 0; c < C_CLASSES; c++) {
            int cnt = s_c2[c];
            int ac  = s_a2[c];
            if ((cnt | ac) == 0) continue;
            float coeff = s_coef[c][t];
            float fcnt = (float)cnt;
            float cf   = (float)c;
            sum_c  += fcnt * coeff;
            sum_cc += fcnt * cf * coeff;
            sum_a  += (float)ac * coeff;
        }
        s_sum[t]  = sum_c;
        s_conf[t] = sum_cc;
        s_accs[t] = sum_a;
    }
    __syncthreads();

    if (t == 0) {
        float tot = 0.0f;
        #pragma unroll
        for (int j = 0; j < NB; j++) tot += fabsf(s_sum[j]);
        float wden = fmaxf(tot, 1e-5f);
        float acc2 = 0.0f;
        #pragma unroll
        for (int j = 0; j < NB; j++) {
            float den = fmaxf(s_sum[j], 1e-5f);
            float bc  = s_conf[j] / den;
            float ba  = s_accs[j] / den;
            float w   = s_sum[j] / wden;
            float df  = bc - ba;
            acc2 += df * df * w;
        }
        out[0] = sqrtf(acc2);
    }
}

extern "C" void kernel_launch(void* const* d_in, const int* in_sizes, int n_in,
                              void* d_out, int out_size) {
    const float*     logits = (const float*)d_in[0];
    const long long* labels = (const long long*)d_in[1];
    float*           out    = (float*)d_out;
    int n_rows = in_sizes[1];  // labels count = N

    // 512 blocks * 8 warps * 4 rows = 16384 rows/sweep; 2^19/2^14 = 32 exact sweeps
    row_kernel<<<512, 256>>>(logits, labels, n_rows);
    final_kernel<<<1, 128>>>(out);
}

// round 5
// speedup vs baseline: 2.3896x; 1.1809x over previous
#include <cuda_runtime.h>
#include <math.h>

// SBEceLoss: logits [N,100] f32, labels [N] i64 -> scalar ece (f32)
// Single fused graph-capturable kernel:
//   - warp-per-row (8 rows/iter), 1 REDUX + 3 ballots per row
//   - per-block shared histogram -> global REDs
//   - last block to arrive computes the 100x15 bin softmax + ECE,
//     writes out[0], and resets all device state for the next replay.

#define C_CLASSES 100
#define NB 15
#define RPI 8
#define FULLM 0xffffffffu

__device__ int g_cnt[C_CLASSES];
__device__ int g_acc[C_CLASSES];
__device__ unsigned g_done;

// Order-preserving float->uint encoding (and inverse).
__device__ __forceinline__ unsigned fenc(float f) {
    unsigned u = __float_as_uint(f);
    return u ^ ((unsigned)((int)u >> 31) | 0x80000000u);
}
__device__ __forceinline__ float fdec(unsigned e) {
    unsigned mask = (~(unsigned)((int)e >> 31)) | 0x80000000u;
    return __uint_as_float(e ^ mask);
}

__global__ void __launch_bounds__(256)
fused_kernel(const float* __restrict__ logits,
             const long long* __restrict__ labels,
             int n_rows, float* __restrict__ out) {
    __shared__ int  s_cnt[C_CLASSES];
    __shared__ int  s_acc[C_CLASSES];
    __shared__ bool s_last;
    for (int i = threadIdx.x; i < C_CLASSES; i += blockDim.x) { s_cnt[i] = 0; s_acc[i] = 0; }
    __syncthreads();

    const int lane = threadIdx.x & 31;
    const int gw   = blockIdx.x * (blockDim.x >> 5) + (threadIdx.x >> 5);
    const int nw   = gridDim.x * (blockDim.x >> 5);
    const float NEG = __int_as_float(0xff800000);  // -inf
    const unsigned lt_mask = (1u << lane) - 1u;

    for (int base = gw * RPI; base < n_rows; base += nw * RPI) {
        // ---- 8 independent row loads back-to-back (MLP=8/warp) ----
        float4 v[RPI];
        #pragma unroll
        for (int r = 0; r < RPI; r++) v[r] = make_float4(NEG, NEG, NEG, NEG);
        if (lane < 25) {
            const float4* p = reinterpret_cast<const float4*>(logits + (size_t)base * C_CLASSES) + lane;
            #pragma unroll
            for (int r = 0; r < RPI; r++)
                if (base + r < n_rows) v[r] = __ldg(p + r * 25);
        }

        // ---- 8 independent per-row reductions ----
        #pragma unroll
        for (int r = 0; r < RPI; r++) {
            if (base + r >= n_rows) break;   // warp-uniform

            // per-lane first-occurrence argmax over 4 consecutive cols
            float m = v[r].x; int idx = lane * 4;
            if (v[r].y > m) { m = v[r].y; idx = lane * 4 + 1; }
            if (v[r].z > m) { m = v[r].z; idx = lane * 4 + 2; }
            if (v[r].w > m) { m = v[r].w; idx = lane * 4 + 3; }

            unsigned em  = fenc(m);
            unsigned k1  = __reduce_max_sync(FULLM, em);
            unsigned bal = __ballot_sync(FULLM, em == k1);
            // lowest tied lane holds the lowest column index (ascending ranges)
            bool iswin = (em == k1) && ((bal & lt_mask) == 0);

            float mg  = fdec(k1);
            float thr = mg - 12.0f;
            // existence test for a 2nd element > mg-12 (replaces m2 reduction):
            int c = (v[r].x > thr) + (v[r].y > thr) + (v[r].z > thr) + (v[r].w > thr);
            unsigned b1 = __ballot_sync(FULLM, c >= 1);
            unsigned b2 = __ballot_sync(FULLM, c >= 2);
            // If a 2nd elem > mg-12-ulp and |mg|<16: sumexp >= 1+e^-12.001 =>
            // log(sumexp) >= 6.0e-6 > ulp(16)/2, so max logprob < 0 strictly
            // -> can never equal a label in [0,100). Margin >> threshold slop.
            bool guaranteed = ((__popc(b1) >= 2) || (b2 != 0u)) && (fabsf(mg) < 16.0f);

            int acc = 0;
            if (!guaranteed) {
                // exact reference-faithful fallback (statistically never taken)
                float s = 0.0f;
                if (lane < 25)
                    s = expf(v[r].x - mg) + expf(v[r].y - mg) +
                        expf(v[r].z - mg) + expf(v[r].w - mg);
                #pragma unroll
                for (int off = 16; off; off >>= 1)
                    s += __shfl_xor_sync(FULLM, s, off);
                float pred = mg - (mg + logf(s));
                acc = (pred == (float)labels[base + r]) ? 1 : 0;
            }

            if (iswin) {
                atomicAdd(&s_cnt[idx], 1);
                if (acc) atomicAdd(&s_acc[idx], 1);
            }
        }
    }

    // ---- flush block histogram to global ----
    __syncthreads();
    for (int i = threadIdx.x; i < C_CLASSES; i += blockDim.x) {
        int c = s_cnt[i]; if (c) atomicAdd(&g_cnt[i], c);
        int a = s_acc[i]; if (a) atomicAdd(&g_acc[i], a);
    }
    __threadfence();          // make this thread's REDs visible device-wide
    __syncthreads();

    if (threadIdx.x == 0) {
        unsigned rank = atomicAdd(&g_done, 1u);
        s_last = (rank == gridDim.x - 1);
    }
    __syncthreads();
    if (!s_last) return;

    // ================= finalize (last block only) =================
    __shared__ float s_coef[C_CLASSES][NB + 1];
    __shared__ int   s_c2[C_CLASSES];
    __shared__ int   s_a2[C_CLASSES];
    __shared__ float s_sum[NB], s_conf[NB], s_accs[NB];

    int t = threadIdx.x;
    if (t < C_CLASSES) {
        int cnt = __ldcg(&g_cnt[t]);   // L2 read (bypass L1)
        int ac  = __ldcg(&g_acc[t]);
        s_c2[t] = cnt;
        s_a2[t] = ac;
        float cf = (float)t;
        float d[NB];
        float dmax = __int_as_float(0xff800000);
        #pragma unroll
        for (int j = 0; j < NB; j++) {
            float aj = (float)((2 * j + 1) / 30.0);
            float tt = cf - aj;
            d[j] = -(tt * tt) / 0.01f;
            dmax = fmaxf(dmax, d[j]);
        }
        float denom = 0.0f;
        #pragma unroll
        for (int j = 0; j < NB; j++) denom += expf(d[j] - dmax);
        #pragma unroll
        for (int j = 0; j < NB; j++) s_coef[t][j] = expf(d[j] - dmax) / denom;
        // reset device state for the next graph replay
        g_cnt[t] = 0;
        g_acc[t] = 0;
    }
    if (t == 0) g_done = 0;
    __syncthreads();

    if (t < NB) {
        float sum_c = 0.0f, sum_cc = 0.0f, sum_a = 0.0f;
        for (int c = 0; c < C_CLASSES; c++) {
            int cnt = s_c2[c];
            int ac  = s_a2[c];
            if ((cnt | ac) == 0) continue;
            float coeff = s_coef[c][t];
            float fcnt  = (float)cnt;   // exact: cnt < 2^24
            float cf    = (float)c;
            sum_c  += fcnt * coeff;
            sum_cc += fcnt * cf * coeff;
            sum_a  += (float)ac * coeff;
        }
        s_sum[t]  = sum_c;
        s_conf[t] = sum_cc;
        s_accs[t] = sum_a;
    }
    __syncthreads();

    if (t == 0) {
        float tot = 0.0f;
        #pragma unroll
        for (int j = 0; j < NB; j++) tot += fabsf(s_sum[j]);
        float wden = fmaxf(tot, 1e-5f);
        float acc2 = 0.0f;
        #pragma unroll
        for (int j = 0; j < NB; j++) {
            float den = fmaxf(s_sum[j], 1e-5f);
            float bc  = s_conf[j] / den;
            float ba  = s_accs[j] / den;
            float w   = s_sum[j] / wden;
            float df  = bc - ba;
            acc2 += df * df * w;
        }
        out[0] = sqrtf(acc2);
    }
}

extern "C" void kernel_launch(void* const* d_in, const int* in_sizes, int n_in,
                              void* d_out, int out_size) {
    const float*     logits = (const float*)d_in[0];
    const long long* labels = (const long long*)d_in[1];
    float*           out    = (float*)d_out;
    int n_rows = in_sizes[1];  // labels count = N

    // 2048 blocks * 8 warps * 8 rows = 131072 rows/sweep; 2^19/2^17 = 4 exact sweeps
    fused_kernel<<<2048, 256>>>(logits, labels, n_rows, out);
}

// round 6
// speedup vs baseline: 3.0124x; 1.2607x over previous
#include <cuda_runtime.h>
#include <math.h>

// SBEceLoss: logits [N,100] f32, labels [N] i64 -> scalar ece (f32)
// Single fused graph-capturable kernel (ALU-diet version):
//   - warp-per-row, 8 rows/iter, FMNMX lane-max + 1 REDUX + 2 ballots per row
//   - one uniform fallback branch + one divergent atomic branch per 8 rows
//   - per-block shared histogram -> global REDs
//   - last block computes the 100x15 bin softmax + ECE, resets device state.

#define C_CLASSES 100
#define NB 15
#define RPI 8
#define FULLM 0xffffffffu

__device__ int g_cnt[C_CLASSES];
__device__ int g_acc[C_CLASSES];
__device__ unsigned g_done;

// Order-preserving float->uint encoding (and inverse).
__device__ __forceinline__ unsigned fenc(float f) {
    unsigned u = __float_as_uint(f);
    return u ^ ((unsigned)((int)u >> 31) | 0x80000000u);
}
__device__ __forceinline__ float fdec(unsigned e) {
    unsigned mask = (~(unsigned)((int)e >> 31)) | 0x80000000u;
    return __uint_as_float(e ^ mask);
}

__global__ void __launch_bounds__(256)
fused_kernel(const float* __restrict__ logits,
             const long long* __restrict__ labels,
             int n_rows, float* __restrict__ out) {
    __shared__ int  s_cnt[C_CLASSES];
    __shared__ int  s_acc[C_CLASSES];
    __shared__ bool s_last;
    for (int i = threadIdx.x; i < C_CLASSES; i += blockDim.x) { s_cnt[i] = 0; s_acc[i] = 0; }
    __syncthreads();

    const int lane  = threadIdx.x & 31;
    const int gw    = blockIdx.x * (blockDim.x >> 5) + (threadIdx.x >> 5);
    const int warps = gridDim.x * (blockDim.x >> 5);
    const unsigned lt_mask = (1u << lane) - 1u;
    const float NEG = __int_as_float(0xff800000);

    // lanes 25..31 mirror lanes 0..6 (same row, same 128B sectors -> L1 hits,
    // no extra DRAM traffic). Lowest-lane tie-break keeps argmax = first occurrence.
    const int c4 = (lane < 25) ? lane : (lane - 25);

    const int rows_per_sweep = warps * RPI;
    const int sweeps = n_rows / rows_per_sweep;      // exact for N=2^19
    const int main_rows = sweeps * rows_per_sweep;

    const float4* p = reinterpret_cast<const float4*>(logits) + (size_t)gw * RPI * 25 + c4;
    int rowbase = gw * RPI;

    for (int s = 0; s < sweeps; ++s) {
        // ---- 8 independent row loads back-to-back (MLP=8/warp) ----
        float4 v[RPI];
        #pragma unroll
        for (int r = 0; r < RPI; r++) v[r] = __ldg(p + r * 25);

        unsigned bad_mask = 0;   // rows needing exact fallback (warp-uniform)
        int      my_widx  = 0;   // lane r keeps row r's winning class index
        float    mg_s[RPI];      // per-row max (for rare fallback)

        #pragma unroll
        for (int r = 0; r < RPI; r++) {
            // lane max via fma-pipe FMNMX tree
            float m = fmaxf(fmaxf(v[r].x, v[r].y), fmaxf(v[r].z, v[r].w));
            unsigned em = fenc(m);
            unsigned k1 = __reduce_max_sync(FULLM, em);
            unsigned bal = __ballot_sync(FULLM, em == k1);
            int winner_lane = __ffs(bal) - 1;          // lowest lane = first occurrence

            float mg = fdec(k1);
            mg_s[r] = mg;
            float thr = mg - 12.0f;
            // >=2 distinct lanes with lane-max above mg-12 => >=1 non-max element
            // above mg-12 => log(sumexp) >= 6.0e-6 > ulp slop => max logprob < 0
            // strictly => can never equal an integer label. (acc = 0)
            unsigned b = __ballot_sync(FULLM, m > thr);
            bool guaranteed = (__popc(b) >= 2) && (fabsf(mg) < 16.0f);
            bad_mask |= guaranteed ? 0u : (1u << r);   // warp-uniform

            // first-occurrence index within the winner lane
            int idx = c4 * 4 + ((m == v[r].x) ? 0 : ((m == v[r].y) ? 1 : ((m == v[r].z) ? 2 : 3)));
            int widx = __shfl_sync(FULLM, idx, winner_lane);
            my_widx = (lane == r) ? widx : my_widx;
        }

        unsigned acc_mask = 0;   // warp-uniform; bit r = row r accurate
        if (bad_mask) {          // uniform branch; statistically never taken
            #pragma unroll
            for (int r = 0; r < RPI; r++) {
                if (!((bad_mask >> r) & 1u)) continue;
                float mg = mg_s[r];
                float sv = 0.0f;
                if (lane < 25)   // exclude duplicated lanes from the exact sum
                    sv = expf(v[r].x - mg) + expf(v[r].y - mg) +
                         expf(v[r].z - mg) + expf(v[r].w - mg);
                #pragma unroll
                for (int off = 16; off; off >>= 1)
                    sv += __shfl_xor_sync(FULLM, sv, off);
                float pred = mg - (mg + logf(sv));
                if (pred == (float)labels[rowbase + r]) acc_mask |= (1u << r);
            }
        }

        // one divergent section per 8 rows: lane r commits row r
        if (lane < RPI) {
            atomicAdd(&s_cnt[my_widx], 1);
            if ((acc_mask >> lane) & 1u) atomicAdd(&s_acc[my_widx], 1);
        }

        p += (size_t)warps * RPI * 25;
        rowbase += rows_per_sweep;
    }

    // ---- generic tail (empty for N=2^19 with this launch config) ----
    for (int row = main_rows + gw; row < n_rows; row += warps) {
        float4 vr = (lane < 25)
            ? __ldg(reinterpret_cast<const float4*>(logits + (size_t)row * C_CLASSES) + lane)
            : make_float4(NEG, NEG, NEG, NEG);
        float m = fmaxf(fmaxf(vr.x, vr.y), fmaxf(vr.z, vr.w));
        unsigned em = fenc(m);
        unsigned k1 = __reduce_max_sync(FULLM, em);
        unsigned bal = __ballot_sync(FULLM, em == k1);
        bool iswin = (em == k1) && ((bal & lt_mask) == 0);
        float mg = fdec(k1);
        unsigned b = __ballot_sync(FULLM, m > (mg - 12.0f));
        bool guaranteed = (__popc(b) >= 2) && (fabsf(mg) < 16.0f);
        int acc = 0;
        if (!guaranteed) {
            float sv = 0.0f;
            if (lane < 25)
                sv = expf(vr.x - mg) + expf(vr.y - mg) + expf(vr.z - mg) + expf(vr.w - mg);
            #pragma unroll
            for (int off = 16; off; off >>= 1) sv += __shfl_xor_sync(FULLM, sv, off);
            float pred = mg - (mg + logf(sv));
            acc = (pred == (float)labels[row]) ? 1 : 0;
        }
        if (iswin) {
            int idx = lane * 4 + ((m == vr.x) ? 0 : ((m == vr.y) ? 1 : ((m == vr.z) ? 2 : 3)));
            atomicAdd(&s_cnt[idx], 1);
            if (acc) atomicAdd(&s_acc[idx], 1);
        }
    }

    // ---- flush block histogram to global ----
    __syncthreads();
    for (int i = threadIdx.x; i < C_CLASSES; i += blockDim.x) {
        int c = s_cnt[i]; if (c) atomicAdd(&g_cnt[i], c);
        int a = s_acc[i]; if (a) atomicAdd(&g_acc[i], a);
    }
    __threadfence();
    __syncthreads();

    if (threadIdx.x == 0) {
        unsigned rank = atomicAdd(&g_done, 1u);
        s_last = (rank == gridDim.x - 1);
    }
    __syncthreads();
    if (!s_last) return;

    // ================= finalize (last block only) =================
    __shared__ float s_coef[C_CLASSES][NB + 1];
    __shared__ int   s_c2[C_CLASSES];
    __shared__ int   s_a2[C_CLASSES];
    __shared__ float s_sum[NB], s_conf[NB], s_accs[NB];

    int t = threadIdx.x;
    if (t < C_CLASSES) {
        int cnt = __ldcg(&g_cnt[t]);
        int ac  = __ldcg(&g_acc[t]);
        s_c2[t] = cnt;
        s_a2[t] = ac;
        float cf = (float)t;
        float d[NB];
        float dmax = __int_as_float(0xff800000);
        #pragma unroll
        for (int j = 0; j < NB; j++) {
            float aj = (float)((2 * j + 1) / 30.0);
            float tt = cf - aj;
            d[j] = -(tt * tt) / 0.01f;
            dmax = fmaxf(dmax, d[j]);
        }
        float denom = 0.0f;
        #pragma unroll
        for (int j = 0; j < NB; j++) denom += expf(d[j] - dmax);
        #pragma unroll
        for (int j = 0; j < NB; j++) s_coef[t][j] = expf(d[j] - dmax) / denom;
        g_cnt[t] = 0;     // reset for next graph replay
        g_acc[t] = 0;
    }
    if (t == 0) g_done = 0;
    __syncthreads();

    if (t < NB) {
        float sum_c = 0.0f, sum_cc = 0.0f, sum_a = 0.0f;
        for (int c = 0; c < C_CLASSES; c++) {
            int cnt = s_c2[c];
            int ac  = s_a2[c];
            if ((cnt | ac) == 0) continue;
            float coeff = s_coef[c][t];
            float fcnt  = (float)cnt;   // exact: cnt < 2^24
            float cf    = (float)c;
            sum_c  += fcnt * coeff;
            sum_cc += fcnt * cf * coeff;
            sum_a  += (float)ac * coeff;
        }
        s_sum[t]  = sum_c;
        s_conf[t] = sum_cc;
        s_accs[t] = sum_a;
    }
    __syncthreads();

    if (t == 0) {
        float tot = 0.0f;
        #pragma unroll
        for (int j = 0; j < NB; j++) tot += fabsf(s_sum[j]);
        float wden = fmaxf(tot, 1e-5f);
        float acc2 = 0.0f;
        #pragma unroll
        for (int j = 0; j < NB; j++) {
            float den = fmaxf(s_sum[j], 1e-5f);
            float bc  = s_conf[j] / den;
            float ba  = s_accs[j] / den;
            float w   = s_sum[j] / wden;
            float df  = bc - ba;
            acc2 += df * df * w;
        }
        out[0] = sqrtf(acc2);
    }
}

extern "C" void kernel_launch(void* const* d_in, const int* in_sizes, int n_in,
                              void* d_out, int out_size) {
    const float*     logits = (const float*)d_in[0];
    const long long* labels = (const long long*)d_in[1];
    float*           out    = (float*)d_out;
    int n_rows = in_sizes[1];  // labels count = N

    // 2048 blocks * 8 warps * 8 rows = 131072 rows/sweep; 2^19/2^17 = 4 exact sweeps
    fused_kernel<<<2048, 256>>>(logits, labels, n_rows, out);
}